// round 4
// baseline (speedup 1.0000x reference)
#include <cuda_runtime.h>
#include <cuda_fp16.h>
#include <cstdint>
#include <cstddef>

// ============================================================
// MovementPrunedLinear: out = x @ (W * blockmask)^T + bias
// x: [8192, 4096] f32, W: [4096, 4096] f32, bias [4096], scores [128,128]
//
// Build constraint discovered R3: harness compiles via compute_103 PTX
// target, so sm_103a-specific (tcgen05/TMEM) PTX is unavailable.
// Strategy: convert x, masked W -> fp16 once; then Ampere-style
// mma.sync m16n8k16 (fp32 accum) GEMM with cp.async 3-stage pipeline
// and SW128-swizzled SMEM.
// ============================================================

#define MM 8192
#define NN 4096
#define KK 4096

#define MT 128
#define NT 128
#define BK 64
#define KTILES (KK / BK)          // 64
#define STAGES 3

#define TILE_A_BYTES (MT * BK * 2)   // 16384
#define TILE_B_BYTES (NT * BK * 2)   // 16384
#define STAGE_BYTES  (TILE_A_BYTES + TILE_B_BYTES)  // 32768
#define SMEM_TOTAL   (STAGES * STAGE_BYTES)         // 98304

// fp16 scratch (static device arrays: allowed by harness rules)
__device__ __align__(128) __half g_Xh[(size_t)MM * KK];
__device__ __align__(128) __half g_Wh[(size_t)NN * KK];

// ---------------- PTX helpers (all compute_103-legal) ----------------
static __device__ __forceinline__ uint32_t smem_u32(const void* p) {
    return (uint32_t)__cvta_generic_to_shared(p);
}
static __device__ __forceinline__ void cp16(uint32_t dst, const void* src) {
    asm volatile("cp.async.cg.shared.global [%0], [%1], 16;" :: "r"(dst), "l"(src));
}
static __device__ __forceinline__ void cp_commit() {
    asm volatile("cp.async.commit_group;" ::: "memory");
}
static __device__ __forceinline__ void cp_wait1() {
    asm volatile("cp.async.wait_group 1;" ::: "memory");
}
static __device__ __forceinline__ void ldsm4(uint32_t& r0, uint32_t& r1,
                                             uint32_t& r2, uint32_t& r3, uint32_t a) {
    asm volatile("ldmatrix.sync.aligned.m8n8.x4.shared.b16 {%0,%1,%2,%3}, [%4];"
                 : "=r"(r0), "=r"(r1), "=r"(r2), "=r"(r3) : "r"(a));
}
static __device__ __forceinline__ void mma16816(float* d, const uint32_t* a,
                                                const uint32_t* b) {
    asm volatile(
        "mma.sync.aligned.m16n8k16.row.col.f32.f16.f16.f32 "
        "{%0,%1,%2,%3}, {%4,%5,%6,%7}, {%8,%9}, {%0,%1,%2,%3};"
        : "+f"(d[0]), "+f"(d[1]), "+f"(d[2]), "+f"(d[3])
        : "r"(a[0]), "r"(a[1]), "r"(a[2]), "r"(a[3]), "r"(b[0]), "r"(b[1]));
}

// ---------------- conversion kernels ----------------
__global__ void __launch_bounds__(256) cvt_x_kernel(const float* __restrict__ x) {
    size_t i = ((size_t)blockIdx.x * 256 + threadIdx.x) * 8;
    float4 a = *reinterpret_cast<const float4*>(x + i);
    float4 b = *reinterpret_cast<const float4*>(x + i + 4);
    __half2 h0 = __floats2half2_rn(a.x, a.y);
    __half2 h1 = __floats2half2_rn(a.z, a.w);
    __half2 h2 = __floats2half2_rn(b.x, b.y);
    __half2 h3 = __floats2half2_rn(b.z, b.w);
    uint4 o;
    o.x = *reinterpret_cast<uint32_t*>(&h0);
    o.y = *reinterpret_cast<uint32_t*>(&h1);
    o.z = *reinterpret_cast<uint32_t*>(&h2);
    o.w = *reinterpret_cast<uint32_t*>(&h3);
    *reinterpret_cast<uint4*>(g_Xh + i) = o;
}

__global__ void __launch_bounds__(256) cvt_w_kernel(const float* __restrict__ w,
                                                    const float* __restrict__ scores) {
    size_t i = ((size_t)blockIdx.x * 256 + threadIdx.x) * 8;
    int orow = (int)(i >> 12);          // / 4096
    int icol = (int)(i & 4095);
    // sigmoid(s) > 0.1  <=>  s > logit(0.1)
    float s = scores[(orow >> 5) * 128 + (icol >> 5)];
    bool active = s > -2.19722457733621938f;
    float4 a = *reinterpret_cast<const float4*>(w + i);
    float4 b = *reinterpret_cast<const float4*>(w + i + 4);
    if (!active) {
        a = make_float4(0.f, 0.f, 0.f, 0.f);
        b = make_float4(0.f, 0.f, 0.f, 0.f);
    }
    __half2 h0 = __floats2half2_rn(a.x, a.y);
    __half2 h1 = __floats2half2_rn(a.z, a.w);
    __half2 h2 = __floats2half2_rn(b.x, b.y);
    __half2 h3 = __floats2half2_rn(b.z, b.w);
    uint4 o;
    o.x = *reinterpret_cast<uint32_t*>(&h0);
    o.y = *reinterpret_cast<uint32_t*>(&h1);
    o.z = *reinterpret_cast<uint32_t*>(&h2);
    o.w = *reinterpret_cast<uint32_t*>(&h3);
    *reinterpret_cast<uint4*>(g_Wh + i) = o;
}

// ---------------- GEMM kernel ----------------
// CTA 128x128, BK=64, 3-stage cp.async pipeline.
// SMEM tile: 128 rows x 128B (64 halves). SW128 swizzle on 16B chunks:
//   byte(r, chunk) = r*128 + (chunk ^ (r & 7)) * 16
// Warps: 8 in 4(M) x 2(N); warp tile 32x64; mma m16n8k16.
__global__ void __launch_bounds__(256, 1) gemm_kernel(const float* __restrict__ bias,
                                                      float* __restrict__ out) {
    extern __shared__ char smem[];
    const uint32_t sb = smem_u32(smem);
    const int tid = threadIdx.x;
    const int wid = tid >> 5;
    const int lid = tid & 31;
    const int m0 = blockIdx.y * MT;
    const int n0 = blockIdx.x * NT;

    // -------- cp.async geometry: thread t loads row t/2, chunks (t&1)*4 + 0..3
    const int ldr = tid >> 1;                 // 0..127
    const int ldc0 = (tid & 1) * 4;           // chunk base
    const __half* gA = g_Xh + (size_t)(m0 + ldr) * KK + ldc0 * 8;
    const __half* gB = g_Wh + (size_t)(n0 + ldr) * KK + ldc0 * 8;
    // destination offsets (swizzled) for the 4 chunks
    uint32_t dA[4];
#pragma unroll
    for (int i = 0; i < 4; i++)
        dA[i] = (uint32_t)(ldr * 128 + (((ldc0 + i) ^ (ldr & 7)) << 4));

    // -------- ldmatrix geometry
    const int wm = wid & 3;                   // M quarter (32 rows)
    const int wn = wid >> 2;                  // N half (64 cols)
    // A: lane -> row (L%16), chunk-sel (L/16)
    const int arow = wm * 32 + (lid & 15);
    const int acs  = lid >> 4;
    const uint32_t aByteBase = (uint32_t)(arow * 128);
    const uint32_t ax = (uint32_t)(arow & 7);
    // B: lane -> row (L&7) + ((L>>4)<<3), chunk-sel (L>>3)&1
    const int brow = wn * 64 + (lid & 7) + ((lid >> 4) << 3);
    const int bcs  = (lid >> 3) & 1;
    const uint32_t bByteBase = (uint32_t)(brow * 128);
    const uint32_t bx = (uint32_t)(brow & 7);

    float acc[2][8][4];
#pragma unroll
    for (int mi = 0; mi < 2; mi++)
#pragma unroll
        for (int nj = 0; nj < 8; nj++)
#pragma unroll
            for (int c = 0; c < 4; c++) acc[mi][nj][c] = 0.0f;

    // -------- prologue: stages 0 and 1
#pragma unroll
    for (int s = 0; s < 2; s++) {
        uint32_t base = sb + s * STAGE_BYTES;
#pragma unroll
        for (int i = 0; i < 4; i++) {
            cp16(base + dA[i], gA + (size_t)s * BK + i * 8);
            cp16(base + TILE_A_BYTES + dA[i], gB + (size_t)s * BK + i * 8);
        }
        cp_commit();
    }

#pragma unroll 1
    for (int t = 0; t < KTILES; t++) {
        cp_wait1();
        __syncthreads();

        // issue loads for stage t+2 into buffer (t+2)%3
        if (t + 2 < KTILES) {
            uint32_t base = sb + ((t + 2) % STAGES) * STAGE_BYTES;
            const __half* sA = gA + (size_t)(t + 2) * BK;
            const __half* sB = gB + (size_t)(t + 2) * BK;
#pragma unroll
            for (int i = 0; i < 4; i++) {
                cp16(base + dA[i], sA + i * 8);
                cp16(base + TILE_A_BYTES + dA[i], sB + i * 8);
            }
        }
        cp_commit();

        // compute from buffer t%3
        const uint32_t aTile = sb + (t % STAGES) * STAGE_BYTES;
        const uint32_t bTile = aTile + TILE_A_BYTES;
#pragma unroll
        for (int ks = 0; ks < 4; ks++) {
            uint32_t afrag[2][4];
#pragma unroll
            for (int mi = 0; mi < 2; mi++) {
                uint32_t addr = aTile + aByteBase + mi * (16 * 128) +
                                ((((uint32_t)(ks * 2 + acs)) ^ ax) << 4);
                ldsm4(afrag[mi][0], afrag[mi][1], afrag[mi][2], afrag[mi][3], addr);
            }
            uint32_t bfrag[8][2];
#pragma unroll
            for (int ni = 0; ni < 4; ni++) {
                uint32_t r0, r1, r2, r3;
                uint32_t addr = bTile + bByteBase + ni * (16 * 128) +
                                ((((uint32_t)(ks * 2 + bcs)) ^ bx) << 4);
                ldsm4(r0, r1, r2, r3, addr);
                bfrag[2 * ni][0] = r0; bfrag[2 * ni][1] = r1;
                bfrag[2 * ni + 1][0] = r2; bfrag[2 * ni + 1][1] = r3;
            }
#pragma unroll
            for (int mi = 0; mi < 2; mi++)
#pragma unroll
                for (int nj = 0; nj < 8; nj++)
                    mma16816(acc[mi][nj], afrag[mi], bfrag[nj]);
        }
    }

    // -------- epilogue: d frag mapping: lane L -> (row L/4 [+8], col (L%4)*2)
    const int qr = lid >> 2;
    const int qc = lid & 3;
    const int colBase = n0 + wn * 64 + qc * 2;
#pragma unroll
    for (int nj = 0; nj < 8; nj++) {
        const int col = colBase + nj * 8;
        const float b0 = __ldg(bias + col);
        const float b1 = __ldg(bias + col + 1);
#pragma unroll
        for (int mi = 0; mi < 2; mi++) {
            const int row = m0 + wm * 32 + mi * 16 + qr;
            float2 v0 = make_float2(acc[mi][nj][0] + b0, acc[mi][nj][1] + b1);
            float2 v1 = make_float2(acc[mi][nj][2] + b0, acc[mi][nj][3] + b1);
            *reinterpret_cast<float2*>(out + (size_t)row * NN + col) = v0;
            *reinterpret_cast<float2*>(out + (size_t)(row + 8) * NN + col) = v1;
        }
    }
}

// ---------------- launch ----------------
extern "C" void kernel_launch(void* const* d_in, const int* in_sizes, int n_in,
                              void* d_out, int out_size) {
    const float* x      = (const float*)d_in[0];
    const float* weight = (const float*)d_in[1];
    const float* bias   = (const float*)d_in[2];
    const float* scores = (const float*)d_in[3];
    float* out = (float*)d_out;

    cvt_x_kernel<<<16384, 256>>>(x);
    cvt_w_kernel<<<8192, 256>>>(weight, scores);

    cudaFuncSetAttribute(gemm_kernel, cudaFuncAttributeMaxDynamicSharedMemorySize, SMEM_TOTAL);
    gemm_kernel<<<dim3(NN / NT, MM / MT, 1), 256, SMEM_TOTAL>>>(bias, out);
}